// round 9
// baseline (speedup 1.0000x reference)
#include <cuda_runtime.h>

#define L_SEQ 256
#define D_HEAD 64
#define MASK_VAL (-4294967295.0f)   // -2^32 + 1
#define ROW_F4 4096                  // 256*64/4 float4 per bhq slab of TMK/TMV
#define BH_F4  4096                  // float4 per (b,h) slab of K/V

#define BARX(id, cnt) asm volatile("bar.sync %0, %1;" :: "r"(id), "r"(cnt) : "memory")

__device__ __forceinline__ void stcs_f(float* p, float v) {
    asm volatile("st.global.cs.f32 [%0], %1;" :: "l"(p), "f"(v) : "memory");
}

// Warp-specialized persistent kernel. 256 threads:
//   group A (tid 0..127):  energy stream (TMK+K) + softmax for row i
//   group B (tid 128..255): aggregation stream (TMV+V) + O store for row i-1
// One rendezvous barrier per row; weights double-buffered in esh_a[2][].
__global__ __launch_bounds__(256, 6)
void tasdp_kernel(const float* __restrict__ Q,
                  const float* __restrict__ Km,
                  const float* __restrict__ V,
                  const float* __restrict__ TMK,
                  const float* __restrict__ TMV,
                  const float* __restrict__ AM,
                  const unsigned char* __restrict__ PM,
                  float* __restrict__ O,
                  float* __restrict__ AW,
                  int H, int write_aw, int total)
{
    __shared__ float  esh_e[L_SEQ];        // energies (A-internal)
    __shared__ float  esh_a[2][L_SEQ];     // weights, double-buffered A->B
    __shared__ float  red_m[4], red_s[4], gred[2];
    __shared__ float4 acc_sh[8][16];       // B-internal

    const int tid  = threadIdx.x;
    const int gtid = tid & 127;            // tid within group
    const int isB  = tid >> 7;             // 0 = group A, 1 = group B
    const int lane = tid & 31;
    const int wg   = gtid >> 5;            // warp within group (0..3)
    const int f4   = gtid & 15;            // float4 chunk within d
    const int hw   = gtid >> 4;            // half-warp id 0..7

    const int bid    = blockIdx.x;
    const int stride = gridDim.x;
    if (bid >= total) return;
    const int n = (total - bid + stride - 1) / stride;   // rows for this CTA

    for (int i = 0; i <= n; ++i) {
        if (!isB) {
            // ---------------- group A: energies + softmax for row_i ----------------
            if (i < n) {
                const int row = bid + i * stride;
                const int q = row & (L_SEQ - 1), bh = row >> 8, b = bh / H;
                const float4 q4 = __ldg((const float4*)(Q + (size_t)row * D_HEAD) + f4);
                const float4* tkp = (const float4*)TMK + (size_t)row * ROW_F4 + hw * 16 + f4;
                const float4* kkp = (const float4*)Km  + (size_t)bh  * BH_F4  + hw * 16 + f4;
                const float*         amrow = AM + q * L_SEQ;
                const unsigned char* pmrow = PM + b * L_SEQ;

                #pragma unroll 4
                for (int it = 0; it < 32; ++it) {
                    float4 tk = __ldcs(tkp);   // streaming
                    float4 kx = __ldg(kkp);    // L2-hot
                    tkp += 128; kkp += 128;    // 8 rows * 16 float4
                    float s = (tk.x + kx.x) * q4.x + (tk.y + kx.y) * q4.y
                            + (tk.z + kx.z) * q4.z + (tk.w + kx.w) * q4.w;
                    s += __shfl_xor_sync(0xffffffffu, s, 1);
                    s += __shfl_xor_sync(0xffffffffu, s, 2);
                    s += __shfl_xor_sync(0xffffffffu, s, 4);
                    s += __shfl_xor_sync(0xffffffffu, s, 8);
                    if (f4 == 0) {
                        const int k = it * 8 + hw;
                        float e = s * 0.125f + amrow[k];
                        if (pmrow[k]) e = MASK_VAL;
                        esh_e[k] = e;
                    }
                }
                BARX(1, 128);                          // A-internal

                // softmax over 256 energies, 128 threads x 2 values
                const float v0 = esh_e[gtid];
                const float v1 = esh_e[gtid + 128];
                float wm = fmaxf(v0, v1);
                #pragma unroll
                for (int o = 16; o > 0; o >>= 1)
                    wm = fmaxf(wm, __shfl_xor_sync(0xffffffffu, wm, o));
                float ws = __expf(v0 - wm) + __expf(v1 - wm);
                #pragma unroll
                for (int o = 16; o > 0; o >>= 1)
                    ws += __shfl_xor_sync(0xffffffffu, ws, o);
                if (lane == 0) { red_m[wg] = wm; red_s[wg] = ws; }
                BARX(1, 128);
                if (wg == 0) {
                    float mi = (lane < 4) ? red_m[lane] : MASK_VAL;
                    float si = (lane < 4) ? red_s[lane] : 0.0f;
                    float gm = mi;
                    gm = fmaxf(gm, __shfl_xor_sync(0xffffffffu, gm, 1));
                    gm = fmaxf(gm, __shfl_xor_sync(0xffffffffu, gm, 2));
                    float z = si * __expf(mi - gm);
                    z += __shfl_xor_sync(0xffffffffu, z, 1);
                    z += __shfl_xor_sync(0xffffffffu, z, 2);
                    if (lane == 0) { gred[0] = gm; gred[1] = 1.0f / z; }
                }
                BARX(1, 128);
                const float m    = gred[0];
                const float invZ = gred[1];
                const float a0 = __expf(v0 - m) * invZ;
                const float a1 = __expf(v1 - m) * invZ;
                const int p = i & 1;
                esh_a[p][gtid]       = a0;
                esh_a[p][gtid + 128] = a1;
                if (write_aw) {
                    stcs_f(AW + (size_t)row * L_SEQ + gtid,       a0);
                    stcs_f(AW + (size_t)row * L_SEQ + gtid + 128, a1);
                }
            }
        } else {
            // ---------------- group B: aggregation + O for row_{i-1} ----------------
            if (i > 0) {
                const int row = bid + (i - 1) * stride;
                const int bh = row >> 8;
                const int p  = (i - 1) & 1;
                const float* aw_s = esh_a[p];
                const float4* tvp = (const float4*)TMV + (size_t)row * ROW_F4 + hw * 16 + f4;
                const float4* vvp = (const float4*)V   + (size_t)bh  * BH_F4  + hw * 16 + f4;
                float4 acc = make_float4(0.f, 0.f, 0.f, 0.f);

                #pragma unroll 4
                for (int it = 0; it < 32; ++it) {
                    float4 tv = __ldcs(tvp);   // streaming
                    float4 vx = __ldg(vvp);    // L2-hot
                    tvp += 128; vvp += 128;
                    const float ak = aw_s[it * 8 + hw];
                    acc.x += ak * (tv.x + vx.x);
                    acc.y += ak * (tv.y + vx.y);
                    acc.z += ak * (tv.z + vx.z);
                    acc.w += ak * (tv.w + vx.w);
                }
                acc_sh[hw][f4] = acc;
                BARX(2, 128);                          // B-internal
                if (gtid < 16) {
                    float4 r = acc_sh[0][gtid];
                    #pragma unroll
                    for (int g = 1; g < 8; ++g) {
                        float4 pp = acc_sh[g][gtid];
                        r.x += pp.x; r.y += pp.y; r.z += pp.z; r.w += pp.w;
                    }
                    ((float4*)(O + (size_t)row * D_HEAD))[gtid] = r;
                }
            }
        }
        if (i < n) BARX(3, 256);                       // rendezvous (A done buf, B done prev)
    }
}

extern "C" void kernel_launch(void* const* d_in, const int* in_sizes, int n_in,
                              void* d_out, int out_size)
{
    const float*         Q   = (const float*)d_in[0];
    const float*         Km  = (const float*)d_in[1];
    const float*         V   = (const float*)d_in[2];
    const float*         TMK = (const float*)d_in[3];
    const float*         TMV = (const float*)d_in[4];
    const float*         AM  = (const float*)d_in[5];
    const unsigned char* PM  = (const unsigned char*)d_in[6];

    const int L = 256, D = 64;
    const int b = in_sizes[6] / L;                 // padding_mask is [b, L]
    const int h = in_sizes[0] / (b * L * D);       // Q is [b, h, L, D]

    const int nO  = b * h * L * D;
    const int nAW = b * h * L * L;
    const int total = b * h * L;

    float* O  = (float*)d_out;
    float* AW = O + nO;
    const int write_aw = (out_size >= nO + nAW) ? 1 : 0;

    int sms = 148;
    cudaDeviceGetAttribute(&sms, cudaDevAttrMultiProcessorCount, 0);
    int grid = sms * 6;
    if (grid > total) grid = total;

    tasdp_kernel<<<grid, 256>>>(Q, Km, V, TMK, TMV, AM, PM, O, AW, h, write_aw, total);
}

// round 10
// speedup vs baseline: 1.3502x; 1.3502x over previous
#include <cuda_runtime.h>

#define L_SEQ 256
#define D_HEAD 64
#define MASK_VAL (-4294967295.0f)   // -2^32 + 1

// One CTA per (b, h, q) row. 256 threads, 6 CTAs/SM.  (R3 + phase-B prefetch)
__global__ __launch_bounds__(256, 6)
void tasdp_kernel(const float* __restrict__ Q,
                  const float* __restrict__ Km,
                  const float* __restrict__ V,
                  const float* __restrict__ TMK,
                  const float* __restrict__ TMV,
                  const float* __restrict__ AM,          // attn_mask [L,L]
                  const unsigned char* __restrict__ PM,  // padding_mask [b,L] (bool)
                  float* __restrict__ O,                 // [b,h,L,D]
                  float* __restrict__ AW,                // [b,h,L,L]
                  int H, int write_aw)
{
    const int bhq = blockIdx.x;          // b*h*L + q  (flattened)
    const int q   = bhq & (L_SEQ - 1);
    const int bh  = bhq >> 8;
    const int b   = bh / H;

    __shared__ float  qsh[D_HEAD];
    __shared__ float  esh[L_SEQ];
    __shared__ float  red[8];
    __shared__ float4 acc_sh[16][16];

    const int tid  = threadIdx.x;
    const int w    = tid >> 5;
    const int lane = tid & 31;
    const int f4   = lane & 15;          // float4 chunk within d (16*4 = 64)
    const int grp  = lane >> 4;          // which of 2 k-rows this half-warp owns

    // ---- load Q row into shared ----
    if (tid < D_HEAD) qsh[tid] = Q[(size_t)bhq * D_HEAD + tid];
    __syncthreads();

    // ---- Phase A: energy[k] = ((K[k] + TMK[q,k]) . Q[q]) / sqrt(d) + mask ----
    const float4 q4 = ((const float4*)qsh)[f4];
    const int krow0 = 2 * w + grp;                 // this half-warp's first k row
    const float4* tptr = (const float4*)(TMK + (size_t)bhq * L_SEQ * D_HEAD)
                         + (krow0 * 16 + f4);
    const float4* kptr = (const float4*)(Km  + (size_t)bh  * L_SEQ * D_HEAD)
                         + (krow0 * 16 + f4);
    const float*         amrow = AM + q * L_SEQ;
    const unsigned char* pmrow = PM + b * L_SEQ;

    #pragma unroll 4
    for (int it = 0; it < L_SEQ / 16; ++it) {
        float4 t  = __ldcs(tptr);      // streaming, no reuse
        float4 kk = __ldg(kptr);       // hot in L2
        tptr += 256;                   // 16 rows * 16 float4
        kptr += 256;
        float s = (t.x + kk.x) * q4.x + (t.y + kk.y) * q4.y
                + (t.z + kk.z) * q4.z + (t.w + kk.w) * q4.w;
        s += __shfl_xor_sync(0xffffffffu, s, 1);
        s += __shfl_xor_sync(0xffffffffu, s, 2);
        s += __shfl_xor_sync(0xffffffffu, s, 4);
        s += __shfl_xor_sync(0xffffffffu, s, 8);
        if (f4 == 0) {
            const int k = it * 16 + krow0;
            float e = s * 0.125f + amrow[k];        // 1/sqrt(64) = 0.125
            if (pmrow[k]) e = MASK_VAL;
            esh[k] = e;
        }
    }

    // ---- Prefetch first phase-B iteration (addresses independent of softmax) ----
    const int bf4 = tid & 15;        // float4 index over d
    const int kg  = tid >> 4;        // 16 k-groups
    const float4* tvp = (const float4*)(TMV + (size_t)bhq * L_SEQ * D_HEAD)
                        + (kg * 16 + bf4);
    const float4* vvp = (const float4*)(V   + (size_t)bh  * L_SEQ * D_HEAD)
                        + (kg * 16 + bf4);
    float4 pf_t = __ldcs(tvp);       // in flight across the softmax window
    float4 pf_v = __ldg(vvp);
    tvp += 256;
    vvp += 256;

    __syncthreads();

    // ---- Softmax over k (256 values, one per thread) ----
    const float v = esh[tid];
    float m = v;
    #pragma unroll
    for (int o = 16; o > 0; o >>= 1)
        m = fmaxf(m, __shfl_xor_sync(0xffffffffu, m, o));
    if (lane == 0) red[w] = m;
    __syncthreads();
    if (tid == 0) {
        float mm = red[0];
        #pragma unroll
        for (int i = 1; i < 8; ++i) mm = fmaxf(mm, red[i]);
        red[0] = mm;
    }
    __syncthreads();
    m = red[0];
    __syncthreads();

    const float e = __expf(v - m);
    float s = e;
    #pragma unroll
    for (int o = 16; o > 0; o >>= 1)
        s += __shfl_xor_sync(0xffffffffu, s, o);
    if (lane == 0) red[w] = s;
    __syncthreads();
    if (tid == 0) {
        float ss = red[0];
        #pragma unroll
        for (int i = 1; i < 8; ++i) ss += red[i];
        red[0] = 1.0f / ss;
    }
    __syncthreads();
    const float a = e * red[0];
    __syncthreads();
    esh[tid] = a;
    if (write_aw) AW[(size_t)bhq * L_SEQ + tid] = a;
    __syncthreads();

    // ---- Phase B: O[q,:] = sum_k a[k] * (V[k,:] + TMV[q,k,:]) ----
    float4 acc;
    {
        const float ak0 = esh[kg];               // consume prefetched iteration
        acc.x = ak0 * (pf_t.x + pf_v.x);
        acc.y = ak0 * (pf_t.y + pf_v.y);
        acc.z = ak0 * (pf_t.z + pf_v.z);
        acc.w = ak0 * (pf_t.w + pf_v.w);
    }

    #pragma unroll 3
    for (int k = kg + 16; k < L_SEQ; k += 16) {
        const float ak = esh[k];
        float4 t  = __ldcs(tvp);     // streaming
        float4 vv = __ldg(vvp);      // hot in L2
        tvp += 256;
        vvp += 256;
        acc.x += ak * (t.x + vv.x);
        acc.y += ak * (t.y + vv.y);
        acc.z += ak * (t.z + vv.z);
        acc.w += ak * (t.w + vv.w);
    }
    acc_sh[kg][bf4] = acc;
    __syncthreads();

    if (tid < 16) {
        float4 r = acc_sh[0][tid];
        #pragma unroll
        for (int g = 1; g < 16; ++g) {
            float4 p = acc_sh[g][tid];
            r.x += p.x; r.y += p.y; r.z += p.z; r.w += p.w;
        }
        ((float4*)(O + (size_t)bhq * D_HEAD))[tid] = r;
    }
}

extern "C" void kernel_launch(void* const* d_in, const int* in_sizes, int n_in,
                              void* d_out, int out_size)
{
    const float*         Q   = (const float*)d_in[0];
    const float*         Km  = (const float*)d_in[1];
    const float*         V   = (const float*)d_in[2];
    const float*         TMK = (const float*)d_in[3];
    const float*         TMV = (const float*)d_in[4];
    const float*         AM  = (const float*)d_in[5];
    const unsigned char* PM  = (const unsigned char*)d_in[6];

    const int L = 256, D = 64;
    const int b = in_sizes[6] / L;                 // padding_mask is [b, L]
    const int h = in_sizes[0] / (b * L * D);       // Q is [b, h, L, D]

    const int nO  = b * h * L * D;
    const int nAW = b * h * L * L;

    float* O  = (float*)d_out;
    float* AW = O + nO;
    const int write_aw = (out_size >= nO + nAW) ? 1 : 0;

    tasdp_kernel<<<b * h * L, 256>>>(Q, Km, V, TMK, TMV, AM, PM, O, AW, h, write_aw);
}